// round 4
// baseline (speedup 1.0000x reference)
#include <cuda_runtime.h>
#include <cstdint>
#include <math.h>

// Problem constants (from reference setup_inputs)
#define T_TOK 4096      // B*S = 2*2048 tokens
#define D_DIM 1024
#define F_DIM 2048
#define E_NUM 8
#define NGRP  9         // group 0 = shared expert, groups 1..8 = routed experts
#define MAXROWS (3*T_TOK)

// ---------------- device scratch ----------------
__device__ int   g_cnt[E_NUM];
__device__ int   g_fill[E_NUM];
__device__ int   g_start[NGRP];
__device__ int   g_gcnt[NGRP];
__device__ int   g_topi[T_TOK * 2];
__device__ float g_topw[T_TOK * 2];
__device__ int   g_tok[MAXROWS];
__device__ float g_wt[MAXROWS];
__device__ int   g_rowof[T_TOK * 2];
__device__ float g_H[(size_t)MAXROWS * F_DIM];   // tf32-rounded gelu(up)
__device__ float g_Y[(size_t)MAXROWS * D_DIM];
// tf32-rounded (rna) operand copies — lets the GEMM inner loop skip cvt entirely
__device__ float g_xr [(size_t)T_TOK * D_DIM];
__device__ float g_Wur[(size_t)E_NUM * D_DIM * F_DIM];
__device__ float g_Wdr[(size_t)E_NUM * F_DIM * D_DIM];
__device__ float g_W1r[(size_t)D_DIM * F_DIM];
__device__ float g_W2r[(size_t)F_DIM * D_DIM];

// ---------------- helpers ----------------
__device__ __forceinline__ uint32_t f2tf(float f) {
    uint32_t u;
    asm("cvt.rna.tf32.f32 %0, %1;" : "=r"(u) : "f"(f));
    return u;
}
__device__ __forceinline__ void mma_tf32(float c[4], const uint32_t a[4],
                                         const uint32_t b[2]) {
    asm("mma.sync.aligned.m16n8k8.row.col.f32.tf32.tf32.f32 "
        "{%0,%1,%2,%3},{%4,%5,%6,%7},{%8,%9},{%0,%1,%2,%3};"
        : "+f"(c[0]), "+f"(c[1]), "+f"(c[2]), "+f"(c[3])
        : "r"(a[0]), "r"(a[1]), "r"(a[2]), "r"(a[3]), "r"(b[0]), "r"(b[1]));
}
__device__ __forceinline__ void cp16(void* smem_dst, const void* gsrc) {
    uint32_t d = (uint32_t)__cvta_generic_to_shared(smem_dst);
    asm volatile("cp.async.ca.shared.global [%0], [%1], 16;\n" ::"r"(d), "l"(gsrc));
}
#define CP_COMMIT() asm volatile("cp.async.commit_group;")
#define CP_WAIT(n)  asm volatile("cp.async.wait_group %0;" ::"n"(n))

// ---------------- small kernels ----------------
__global__ void init_kernel() {
    int i = threadIdx.x;
    if (i < E_NUM) { g_cnt[i] = 0; g_fill[i] = 0; }
}

__global__ void round_kernel(const float* __restrict__ src,
                             float* __restrict__ dst, int n4) {
    int i = blockIdx.x * blockDim.x + threadIdx.x;
    if (i >= n4) return;
    float4 v = ((const float4*)src)[i];
    v.x = __uint_as_float(f2tf(v.x));
    v.y = __uint_as_float(f2tf(v.y));
    v.z = __uint_as_float(f2tf(v.z));
    v.w = __uint_as_float(f2tf(v.w));
    ((float4*)dst)[i] = v;
}

__global__ void router_kernel(const float* __restrict__ x,
                              const float* __restrict__ Wg) {
    int warp = (blockIdx.x * blockDim.x + threadIdx.x) >> 5;
    int lane = threadIdx.x & 31;
    if (warp >= T_TOK) return;
    const float* xr = x + (size_t)warp * D_DIM;
    float acc[E_NUM];
#pragma unroll
    for (int e = 0; e < E_NUM; e++) acc[e] = 0.f;
    for (int i = 0; i < D_DIM / 32; i++) {
        int d = i * 32 + lane;
        float xv = xr[d];
        const float4* wr = (const float4*)(Wg + (size_t)d * E_NUM);
        float4 w0 = wr[0], w1 = wr[1];
        acc[0] += xv * w0.x; acc[1] += xv * w0.y;
        acc[2] += xv * w0.z; acc[3] += xv * w0.w;
        acc[4] += xv * w1.x; acc[5] += xv * w1.y;
        acc[6] += xv * w1.z; acc[7] += xv * w1.w;
    }
#pragma unroll
    for (int e = 0; e < E_NUM; e++)
#pragma unroll
        for (int o = 16; o > 0; o >>= 1)
            acc[e] += __shfl_down_sync(0xffffffffu, acc[e], o);
    if (lane == 0) {
        int b0 = -1, b1 = -1;
        float v0 = -1e30f, v1 = -1e30f;
#pragma unroll
        for (int e = 0; e < E_NUM; e++) {
            float v = acc[e];
            if (v > v0) { v1 = v0; b1 = b0; v0 = v; b0 = e; }
            else if (v > v1) { v1 = v; b1 = e; }
        }
        float w0 = 1.f / (1.f + expf(v1 - v0));
        g_topi[warp * 2 + 0] = b0; g_topw[warp * 2 + 0] = w0;
        g_topi[warp * 2 + 1] = b1; g_topw[warp * 2 + 1] = 1.f - w0;
        atomicAdd(&g_cnt[b0], 1);
        atomicAdd(&g_cnt[b1], 1);
    }
}

__global__ void scan_kernel() {
    g_start[0] = 0; g_gcnt[0] = T_TOK;
    int off = T_TOK;
    for (int e = 0; e < E_NUM; e++) {
        g_start[e + 1] = off;
        g_gcnt[e + 1]  = g_cnt[e];
        off += g_cnt[e];
    }
}

__global__ void fill_kernel() {
    int t = blockIdx.x * blockDim.x + threadIdx.x;
    if (t >= T_TOK) return;
    g_tok[t] = t; g_wt[t] = 1.f;
#pragma unroll
    for (int j = 0; j < 2; j++) {
        int e = g_topi[t * 2 + j];
        int r = g_start[e + 1] + atomicAdd(&g_fill[e], 1);
        g_tok[r] = t;
        g_wt[r]  = g_topw[t * 2 + j];
        g_rowof[t * 2 + j] = r;
    }
}

__device__ __forceinline__ float gelu_erf(float v) {
    return 0.5f * v * (1.f + erff(v * 0.70710678118654752440f));
}

// ---------------- grouped TF32 tensor-core GEMM ----------------
// 128x128 tile, BK=16, 8 warps (2x4 grid, 64x32 warp tiles), mma m16n8k8.
// 4-stage cp.async pipeline, wait_group 2 (only ever blocks on a 3-old group).
// Operands are pre-rounded to tf32 (rna) in GMEM -> no cvt in the hot loop.
#define STAGES 4
#define A_STRIDE 20
#define B_STRIDE 136
#define A_STG_FLT (128 * A_STRIDE)          // 2560 floats
#define B_STG_FLT (16 * B_STRIDE)           // 2176 floats
#define STG_FLT   (A_STG_FLT + B_STG_FLT)   // 4736 floats = 18944 B
#define SMEM_SZ   (STAGES * STG_FLT * 4)    // 75776 B

template<int KDIM, int NDIM, bool UP>
__global__ __launch_bounds__(256, 2)
void grouped_gemm_tf32(const float* __restrict__ X,
                       const float* __restrict__ Bexp,
                       const float* __restrict__ Bsh) {
    extern __shared__ float smem[];

    const int g   = blockIdx.z;
    const int cnt = g_gcnt[g];
    const int m0  = blockIdx.x * 128;
    if (m0 >= cnt) return;
    const int start = g_start[g];
    const int n0    = blockIdx.y * 128;

    const float* __restrict__ B =
        (g == 0) ? Bsh : (Bexp + (size_t)(g - 1) * KDIM * NDIM);
    const float* __restrict__ Asrc = UP ? X : g_H;
    float* __restrict__ Cdst = UP ? g_H : g_Y;

    const int tid  = threadIdx.x;
    const int warp = tid >> 5;
    const int lane = tid & 31;
    const int gid  = lane >> 2;   // 0..7
    const int tig  = lane & 3;    // 0..3
    const int wm   = (warp >> 2) * 64;
    const int wn   = (warp & 3) * 32;

    // --- load geometry ---
    const int ra  = tid >> 2;           // A rows ra, ra+64
    const int c4a = (tid & 3) * 4;
    const int rb  = tid >> 5;           // B rows rb, rb+8
    const int c4b = (tid & 31) * 4;

    int gr0 = m0 + ra;       if (gr0 >= cnt) gr0 = cnt - 1;
    int gr1 = m0 + ra + 64;  if (gr1 >= cnt) gr1 = cnt - 1;
    int sr0, sr1;
    if (UP) { sr0 = g_tok[start + gr0]; sr1 = g_tok[start + gr1]; }
    else    { sr0 = start + gr0;        sr1 = start + gr1; }
    const float* pA0 = Asrc + (size_t)sr0 * KDIM + c4a;
    const float* pA1 = Asrc + (size_t)sr1 * KDIM + c4a;
    const float* pB  = B + n0 + c4b;

    float c[4][4][4];
#pragma unroll
    for (int i = 0; i < 4; i++)
#pragma unroll
        for (int j = 0; j < 4; j++)
#pragma unroll
            for (int k = 0; k < 4; k++) c[i][j][k] = 0.f;

    const int KT = KDIM / 16;

    // stage pointers
    float* As[STAGES];
    float* Bs[STAGES];
#pragma unroll
    for (int s = 0; s < STAGES; s++) {
        As[s] = smem + s * STG_FLT;
        Bs[s] = As[s] + A_STG_FLT;
    }

    // prologue: issue stages 0..2
#pragma unroll
    for (int s = 0; s < STAGES - 1; s++) {
        const int kb = s * 16;
        cp16(&As[s][ra * A_STRIDE + c4a],        pA0 + kb);
        cp16(&As[s][(ra + 64) * A_STRIDE + c4a], pA1 + kb);
        cp16(&Bs[s][rb * B_STRIDE + c4b],        pB + (size_t)(kb + rb) * NDIM);
        cp16(&Bs[s][(rb + 8) * B_STRIDE + c4b],  pB + (size_t)(kb + rb + 8) * NDIM);
        CP_COMMIT();
    }

    for (int kt = 0; kt < KT; kt++) {
        CP_WAIT(STAGES - 2);          // stage kt's group has landed
        __syncthreads();              // everyone done reading buf (kt-1)%4 too

        // issue stage kt+3 into the buffer freed by stage kt-1
        const int kn = kt + STAGES - 1;
        if (kn < KT) {
            const int s  = kn & (STAGES - 1);
            const int kb = kn * 16;
            cp16(&As[s][ra * A_STRIDE + c4a],        pA0 + kb);
            cp16(&As[s][(ra + 64) * A_STRIDE + c4a], pA1 + kb);
            cp16(&Bs[s][rb * B_STRIDE + c4b],        pB + (size_t)(kb + rb) * NDIM);
            cp16(&Bs[s][(rb + 8) * B_STRIDE + c4b],  pB + (size_t)(kb + rb + 8) * NDIM);
        }
        CP_COMMIT();                  // commit even if empty (keeps group count uniform)

        const float* __restrict__ Ac = As[kt & (STAGES - 1)];
        const float* __restrict__ Bc = Bs[kt & (STAGES - 1)];
#pragma unroll
        for (int ks = 0; ks < 2; ks++) {
            uint32_t af[4][4], bf[4][2];
            const int kb = ks * 8;
#pragma unroll
            for (int mt = 0; mt < 4; mt++) {
                int row = wm + mt * 16 + gid;
                af[mt][0] = __float_as_uint(Ac[row * A_STRIDE + kb + tig]);
                af[mt][1] = __float_as_uint(Ac[(row + 8) * A_STRIDE + kb + tig]);
                af[mt][2] = __float_as_uint(Ac[row * A_STRIDE + kb + tig + 4]);
                af[mt][3] = __float_as_uint(Ac[(row + 8) * A_STRIDE + kb + tig + 4]);
            }
#pragma unroll
            for (int nt = 0; nt < 4; nt++) {
                int col = wn + nt * 8 + gid;
                bf[nt][0] = __float_as_uint(Bc[(kb + tig) * B_STRIDE + col]);
                bf[nt][1] = __float_as_uint(Bc[(kb + tig + 4) * B_STRIDE + col]);
            }
#pragma unroll
            for (int mt = 0; mt < 4; mt++)
#pragma unroll
                for (int nt = 0; nt < 4; nt++)
                    mma_tf32(c[mt][nt], af[mt], bf[nt]);
        }
    }

    // ---------------- epilogue ----------------
#pragma unroll
    for (int mt = 0; mt < 4; mt++) {
        int r0 = m0 + wm + mt * 16 + gid;
        int r1 = r0 + 8;
        float w0 = 1.f, w1 = 1.f;
        if (!UP) {
            if (r0 < cnt) w0 = g_wt[start + r0];
            if (r1 < cnt) w1 = g_wt[start + r1];
        }
#pragma unroll
        for (int nt = 0; nt < 4; nt++) {
            int col = n0 + wn + nt * 8 + tig * 2;
            if (r0 < cnt) {
                float2 v;
                if (UP) {   // gelu then round to tf32 so the down-GEMM sees rna values
                    v.x = __uint_as_float(f2tf(gelu_erf(c[mt][nt][0])));
                    v.y = __uint_as_float(f2tf(gelu_erf(c[mt][nt][1])));
                } else {
                    v.x = c[mt][nt][0] * w0; v.y = c[mt][nt][1] * w0;
                }
                *(float2*)(Cdst + (size_t)(start + r0) * NDIM + col) = v;
            }
            if (r1 < cnt) {
                float2 v;
                if (UP) {
                    v.x = __uint_as_float(f2tf(gelu_erf(c[mt][nt][2])));
                    v.y = __uint_as_float(f2tf(gelu_erf(c[mt][nt][3])));
                } else {
                    v.x = c[mt][nt][2] * w1; v.y = c[mt][nt][3] * w1;
                }
                *(float2*)(Cdst + (size_t)(start + r1) * NDIM + col) = v;
            }
        }
    }
}

// ---------------- combine ----------------
__global__ void combine_kernel(float* __restrict__ out) {
    int i = blockIdx.x * blockDim.x + threadIdx.x;
    if (i >= T_TOK * (D_DIM / 4)) return;
    int t  = i / (D_DIM / 4);
    int c4 = i - t * (D_DIM / 4);
    int r0 = g_rowof[t * 2 + 0];
    int r1 = g_rowof[t * 2 + 1];
    float4 s = ((const float4*)(g_Y + (size_t)t  * D_DIM))[c4];
    float4 a = ((const float4*)(g_Y + (size_t)r0 * D_DIM))[c4];
    float4 b = ((const float4*)(g_Y + (size_t)r1 * D_DIM))[c4];
    float4 o;
    o.x = s.x + a.x + b.x;
    o.y = s.y + a.y + b.y;
    o.z = s.z + a.z + b.z;
    o.w = s.w + a.w + b.w;
    ((float4*)out)[i] = o;
}

// ---------------- launcher ----------------
static float* dev_ptr(const void* sym) {
    void* p = nullptr;
    cudaGetSymbolAddress(&p, (const void*)sym);
    return (float*)p;
}

extern "C" void kernel_launch(void* const* d_in, const int* in_sizes, int n_in,
                              void* d_out, int out_size) {
    const float* x  = (const float*)d_in[0];
    const float* Wg = (const float*)d_in[1];
    const float* Wu = (const float*)d_in[2];
    const float* Wd = (const float*)d_in[3];
    const float* W1 = (const float*)d_in[4];
    const float* W2 = (const float*)d_in[5];
    float* out = (float*)d_out;

    static int configured = 0;
    if (!configured) {
        cudaFuncSetAttribute(grouped_gemm_tf32<D_DIM, F_DIM, true>,
                             cudaFuncAttributeMaxDynamicSharedMemorySize, SMEM_SZ);
        cudaFuncSetAttribute(grouped_gemm_tf32<F_DIM, D_DIM, false>,
                             cudaFuncAttributeMaxDynamicSharedMemorySize, SMEM_SZ);
        configured = 1;
    }

    float* xr  = dev_ptr(g_xr);
    float* Wur = dev_ptr(g_Wur);
    float* Wdr = dev_ptr(g_Wdr);
    float* W1r = dev_ptr(g_W1r);
    float* W2r = dev_ptr(g_W2r);

    init_kernel<<<1, 32>>>();
    router_kernel<<<T_TOK / 8, 256>>>(x, Wg);
    scan_kernel<<<1, 1>>>();
    fill_kernel<<<(T_TOK + 255) / 256, 256>>>();

    // pre-round operands to tf32 (rna) once -> hot loop needs no cvt
    {
        int n;
        n = T_TOK * D_DIM / 4;          round_kernel<<<(n + 255) / 256, 256>>>(x,  xr,  n);
        n = E_NUM * D_DIM * F_DIM / 4;  round_kernel<<<(n + 255) / 256, 256>>>(Wu, Wur, n);
        n = E_NUM * F_DIM * D_DIM / 4;  round_kernel<<<(n + 255) / 256, 256>>>(Wd, Wdr, n);
        n = D_DIM * F_DIM / 4;          round_kernel<<<(n + 255) / 256, 256>>>(W1, W1r, n);
        n = F_DIM * D_DIM / 4;          round_kernel<<<(n + 255) / 256, 256>>>(W2, W2r, n);
    }

    grouped_gemm_tf32<D_DIM, F_DIM, true>
        <<<dim3(T_TOK / 128, F_DIM / 128, NGRP), 256, SMEM_SZ>>>(xr, Wur, W1r);

    grouped_gemm_tf32<F_DIM, D_DIM, false>
        <<<dim3(T_TOK / 128, D_DIM / 128, NGRP), 256, SMEM_SZ>>>(nullptr, Wdr, W2r);

    combine_kernel<<<(T_TOK * (D_DIM / 4) + 255) / 256, 256>>>(out);
}